// round 3
// baseline (speedup 1.0000x reference)
#include <cuda_runtime.h>

// SparseSelfAttention: BS=2,H=16,S=4096,D=64, BLOCK=64, 256 global keys.
// Per query: softmax over [64 local | 256 global] scores (duplicates included,
// matching reference), then P @ [Vlocal | Vglobal].

#define BSZ    2
#define HEADS  16
#define SEQ    4096
#define DIM    64
#define BLK    64
#define NB     (SEQ / BLK)      // 64
#define NCHUNK 5                // 1 local + 4 global chunks of 64 keys
#define NEGV   -10000.0f

#define NTHREADS 256
#define KSTRIDE  68             // padded K/V smem row stride (odd 16B-quad stride)
#define SSTRIDE  320            // score row stride

// key position for chunk c, slot k, query-block qblk
__device__ __forceinline__ int key_pos(int c, int k, int qblk) {
    if (c == 0) return qblk * BLK + k;          // local chunk
    int g   = (c - 1) * 64 + k;                 // global key index 0..255
    int blk = g >> 2;
    int off = g & 3;                            // {0,61,62,63}
    return blk * BLK + (off == 0 ? 0 : 60 + off);
}

extern __shared__ float smem[];

__global__ __launch_bounds__(NTHREADS)
void sparse_attn_kernel(const float* __restrict__ Q,
                        const float* __restrict__ K,
                        const float* __restrict__ V,
                        const float* __restrict__ Mask,
                        float* __restrict__ Out)
{
    float* s_scores = smem;                        // 64 * 320
    float* s_q      = s_scores + 64 * SSTRIDE;     // 64 * 64
    float* s_kv     = s_q + 64 * DIM;              // 64 * 68
    float* s_kmask  = s_kv + 64 * KSTRIDE;         // 64
    float* s_lsum   = s_kmask + 64;                // 64

    const int qblk = blockIdx.x;
    const int h    = blockIdx.y;
    const int b    = blockIdx.z;
    const int bh   = b * HEADS + h;
    const size_t base  = (size_t)bh * SEQ * DIM;
    const int    qbase = qblk * BLK;

    const int t    = threadIdx.x;
    const int lane = t & 31;
    const int warp = t >> 5;

    // ---- load Q block (64 x 64 floats), stride 64 (broadcast-only reads) ----
    {
        const float4* src = (const float4*)(Q + base + (size_t)qbase * DIM);
        float4* dst = (float4*)s_q;
        #pragma unroll
        for (int i = 0; i < (64 * DIM / 4) / NTHREADS; i++)
            dst[t + i * NTHREADS] = src[t + i * NTHREADS];
    }

    // ================= phase 1: scores =================
    for (int c = 0; c < NCHUNK; c++) {
        __syncthreads();  // previous-chunk readers done (also covers Q-load on c=0 via next sync)
        // load K chunk: 64 rows x 64 floats, scattered rows, contiguous 256B each
        for (int i = t; i < 64 * 16; i += NTHREADS) {
            int row = i >> 4, c4 = i & 15;
            int pos = key_pos(c, row, qblk);
            float4 val = *(const float4*)(K + base + (size_t)pos * DIM + c4 * 4);
            *(float4*)(s_kv + row * KSTRIDE + c4 * 4) = val;
        }
        if (t < 64) {
            int pos = key_pos(c, t, qblk);
            s_kmask[t] = (Mask[b * SEQ + pos] == 0.0f) ? NEGV : 0.0f;
        }
        __syncthreads();

        // warp handles queries warp*8..+7; lane handles keys {lane, lane+32}
        float acc0[8], acc1[8];
        #pragma unroll
        for (int i = 0; i < 8; i++) { acc0[i] = 0.f; acc1[i] = 0.f; }

        #pragma unroll 4
        for (int d0 = 0; d0 < DIM; d0 += 4) {
            float4 kf0 = *(const float4*)(s_kv + lane * KSTRIDE + d0);
            float4 kf1 = *(const float4*)(s_kv + (lane + 32) * KSTRIDE + d0);
            #pragma unroll
            for (int i = 0; i < 8; i++) {
                float4 qf = *(const float4*)(s_q + (warp * 8 + i) * DIM + d0);
                acc0[i] += qf.x * kf0.x + qf.y * kf0.y + qf.z * kf0.z + qf.w * kf0.w;
                acc1[i] += qf.x * kf1.x + qf.y * kf1.y + qf.z * kf1.z + qf.w * kf1.w;
            }
        }
        float m0 = s_kmask[lane], m1 = s_kmask[lane + 32];
        #pragma unroll
        for (int i = 0; i < 8; i++) {
            s_scores[(warp * 8 + i) * SSTRIDE + c * 64 + lane]      = acc0[i] + m0;
            s_scores[(warp * 8 + i) * SSTRIDE + c * 64 + lane + 32] = acc1[i] + m1;
        }
    }
    __syncthreads();

    // ================= softmax (warp-local rows; store unnormalized exp) =================
    #pragma unroll
    for (int i = 0; i < 8; i++) {
        int q = warp * 8 + i;
        float* row = s_scores + q * SSTRIDE;
        float m = -1e30f;
        #pragma unroll
        for (int j = 0; j < 10; j++) m = fmaxf(m, row[lane + j * 32]);
        #pragma unroll
        for (int o = 16; o > 0; o >>= 1) m = fmaxf(m, __shfl_xor_sync(0xffffffffu, m, o));
        float sum = 0.f;
        #pragma unroll
        for (int j = 0; j < 10; j++) {
            float e = __expf(row[lane + j * 32] - m);
            row[lane + j * 32] = e;
            sum += e;
        }
        #pragma unroll
        for (int o = 16; o > 0; o >>= 1) sum += __shfl_xor_sync(0xffffffffu, sum, o);
        if (lane == 0) s_lsum[q] = sum;
    }

    // ================= phase 2: P @ V =================
    // warp owns queries warp*8..+7; lane owns output cols {2*lane, 2*lane+1}
    float o0[8], o1[8];
    #pragma unroll
    for (int i = 0; i < 8; i++) { o0[i] = 0.f; o1[i] = 0.f; }

    for (int c = 0; c < NCHUNK; c++) {
        __syncthreads();  // also makes softmax writes (s_lsum) visible on c=0
        for (int i = t; i < 64 * 16; i += NTHREADS) {
            int row = i >> 4, c4 = i & 15;
            int pos = key_pos(c, row, qblk);
            float4 val = *(const float4*)(V + base + (size_t)pos * DIM + c4 * 4);
            *(float4*)(s_kv + row * KSTRIDE + c4 * 4) = val;
        }
        __syncthreads();

        #pragma unroll 4
        for (int k = 0; k < 64; k += 2) {
            float2 vf0 = *(const float2*)(s_kv + k * KSTRIDE + 2 * lane);
            float2 vf1 = *(const float2*)(s_kv + (k + 1) * KSTRIDE + 2 * lane);
            #pragma unroll
            for (int i = 0; i < 8; i++) {
                float2 p = *(const float2*)(s_scores + (warp * 8 + i) * SSTRIDE + c * 64 + k);
                o0[i] += p.x * vf0.x + p.y * vf1.x;
                o1[i] += p.x * vf0.y + p.y * vf1.y;
            }
        }
    }

    // ---- normalize + store (coalesced float2) ----
    {
        float* outp = Out + base + (size_t)qbase * DIM;
        #pragma unroll
        for (int i = 0; i < 8; i++) {
            float inv = 1.0f / s_lsum[warp * 8 + i];
            float2 r;
            r.x = o0[i] * inv;
            r.y = o1[i] * inv;
            *(float2*)(outp + (warp * 8 + i) * DIM + 2 * lane) = r;
        }
    }
}

extern "C" void kernel_launch(void* const* d_in, const int* in_sizes, int n_in,
                              void* d_out, int out_size)
{
    const float* Q = (const float*)d_in[0];
    const float* K = (const float*)d_in[1];
    const float* V = (const float*)d_in[2];
    const float* M = (const float*)d_in[3];
    float* O = (float*)d_out;

    int smem_bytes = (64 * SSTRIDE + 64 * DIM + 64 * KSTRIDE + 64 + 64) * (int)sizeof(float);
    cudaFuncSetAttribute(sparse_attn_kernel,
                         cudaFuncAttributeMaxDynamicSharedMemorySize, smem_bytes);

    dim3 grid(NB, HEADS, BSZ);
    sparse_attn_kernel<<<grid, NTHREADS, smem_bytes>>>(Q, K, V, M, O);
}

// round 4
// speedup vs baseline: 3.1361x; 3.1361x over previous
#include <cuda_runtime.h>

// SparseSelfAttention: BS=2,H=16,S=4096,D=64, BLOCK=64, 256 global keys.
// Flash-style fused: per 64-key chunk do QK -> exp -> PV, no score buffer.
// No max-subtraction (scores bounded ~|s|<60; exp fits fp32 comfortably).
// All FMAs are packed fma.rn.f32x2 over query pairs.

#define BSZ    2
#define HEADS  16
#define SEQ    4096
#define DIM    64
#define BLK    64
#define NB     (SEQ / BLK)
#define NCHUNK 5
#define NEGV   -10000.0f

#define NTHREADS 256
#define STRD     68        // smem row stride in floats (odd 16B-quad stride)

typedef unsigned long long u64;

__device__ __forceinline__ u64 pk2(float a, float b) {
    u64 r;
    asm("mov.b64 %0, {%1, %2};" : "=l"(r) : "f"(a), "f"(b));
    return r;
}
__device__ __forceinline__ void upk2(u64 p, float& a, float& b) {
    asm("mov.b64 {%0, %1}, %2;" : "=f"(a), "=f"(b) : "l"(p));
}
__device__ __forceinline__ u64 fma2(u64 a, u64 b, u64 c) {
    u64 d;
    asm("fma.rn.f32x2 %0, %1, %2, %3;" : "=l"(d) : "l"(a), "l"(b), "l"(c));
    return d;
}
__device__ __forceinline__ u64 add2(u64 a, u64 b) {
    u64 d;
    asm("add.rn.f32x2 %0, %1, %2;" : "=l"(d) : "l"(a), "l"(b));
    return d;
}

// key position for chunk c, slot k, query-block qblk
__device__ __forceinline__ int key_pos(int c, int k, int qblk) {
    if (c == 0) return qblk * BLK + k;          // local chunk
    int g   = (c - 1) * 64 + k;                 // global key index 0..255
    int blk = g >> 2;
    int off = g & 3;                            // {0,61,62,63}
    return blk * BLK + (off == 0 ? 0 : 60 + off);
}

extern __shared__ float smem[];

__global__ __launch_bounds__(NTHREADS, 3)
void sparse_attn_kernel(const float* __restrict__ Q,
                        const float* __restrict__ K,
                        const float* __restrict__ V,
                        const float* __restrict__ Mask,
                        float* __restrict__ Out)
{
    float* s_qT = smem;                  // [64 d][STRD]  Q transposed: s_qT[d][q]
    float* s_k  = s_qT + 64 * STRD;      // [64 k][STRD]  K natural: s_k[k][d]
    float* s_v  = s_k  + 64 * STRD;      // [64 k][STRD]  V natural
    float* pT   = s_v  + 64 * STRD;      // [64 k][STRD]  P transposed: pT[k][q]
    float* s_km = pT   + 64 * STRD;      // [64] additive key mask

    const int qblk = blockIdx.x;
    const int h    = blockIdx.y;
    const int b    = blockIdx.z;
    const size_t base  = ((size_t)(b * HEADS + h)) * SEQ * DIM;
    const int    qbase = qblk * BLK;

    const int t    = threadIdx.x;
    const int lane = t & 31;
    const int warp = t >> 5;
    const int qw   = warp * 8;           // warp's first query row

    // ---- load Q block transposed into s_qT[d][q] ----
    #pragma unroll
    for (int i = 0; i < 4; i++) {
        int idx = t + i * NTHREADS;          // 0..1023 float4s
        int q   = idx >> 4;
        int c4  = idx & 15;
        float4 f = *(const float4*)(Q + base + (size_t)(qbase + q) * DIM + c4 * 4);
        s_qT[(4 * c4 + 0) * STRD + q] = f.x;
        s_qT[(4 * c4 + 1) * STRD + q] = f.y;
        s_qT[(4 * c4 + 2) * STRD + q] = f.z;
        s_qT[(4 * c4 + 3) * STRD + q] = f.w;
    }

    // packed accumulators: index [j][dd], j = query-pair 0..3, dd = 0 (d=lane) / 1 (d=lane+32)
    u64 o[4][2];
    u64 psum[4];
    #pragma unroll
    for (int j = 0; j < 4; j++) { o[j][0] = 0ull; o[j][1] = 0ull; psum[j] = 0ull; }

    for (int c = 0; c < NCHUNK; c++) {
        __syncthreads();   // previous chunk's s_k/s_v readers done (covers Q load on c=0 via next sync)

        // load K and V chunks (64 rows x 256B, scattered rows)
        #pragma unroll
        for (int i = 0; i < 4; i++) {
            int idx = t + i * NTHREADS;      // 0..1023
            int row = idx >> 4;
            int c4  = idx & 15;
            int pos = key_pos(c, row, qblk);
            float4 kf = *(const float4*)(K + base + (size_t)pos * DIM + c4 * 4);
            *(float4*)(s_k + row * STRD + c4 * 4) = kf;
            float4 vf = *(const float4*)(V + base + (size_t)pos * DIM + c4 * 4);
            *(float4*)(s_v + row * STRD + c4 * 4) = vf;
        }
        if (t < 64) {
            int pos = key_pos(c, t, qblk);
            s_km[t] = (Mask[b * SEQ + pos] == 0.0f) ? NEGV : 0.0f;
        }
        __syncthreads();

        // ---- QK: acc[j][key] pairs over (q2j, q2j+1); lane owns keys {lane, lane+32} ----
        u64 acc[4][2];
        #pragma unroll
        for (int j = 0; j < 4; j++) { acc[j][0] = 0ull; acc[j][1] = 0ull; }

        #pragma unroll 4
        for (int d0 = 0; d0 < DIM; d0 += 4) {
            float4 k0 = *(const float4*)(s_k + lane * STRD + d0);
            float4 k1 = *(const float4*)(s_k + (lane + 32) * STRD + d0);
            const float* kp0 = (const float*)&k0;
            const float* kp1 = (const float*)&k1;
            #pragma unroll
            for (int dd = 0; dd < 4; dd++) {
                u64 k0d = pk2(kp0[dd], kp0[dd]);
                u64 k1d = pk2(kp1[dd], kp1[dd]);
                const float* qrow = s_qT + (d0 + dd) * STRD + qw;
                ulonglong2 qA = *(const ulonglong2*)(qrow);       // pairs (q0,q1),(q2,q3)
                ulonglong2 qB = *(const ulonglong2*)(qrow + 4);   // pairs (q4,q5),(q6,q7)
                acc[0][0] = fma2(qA.x, k0d, acc[0][0]);
                acc[0][1] = fma2(qA.x, k1d, acc[0][1]);
                acc[1][0] = fma2(qA.y, k0d, acc[1][0]);
                acc[1][1] = fma2(qA.y, k1d, acc[1][1]);
                acc[2][0] = fma2(qB.x, k0d, acc[2][0]);
                acc[2][1] = fma2(qB.x, k1d, acc[2][1]);
                acc[3][0] = fma2(qB.y, k0d, acc[3][0]);
                acc[3][1] = fma2(qB.y, k1d, acc[3][1]);
            }
        }

        // ---- mask + exp (no max subtraction) + write pT[k][q] + row-sum ----
        {
            float m0 = s_km[lane];
            float m1 = s_km[lane + 32];
            #pragma unroll
            for (int j = 0; j < 4; j++) {
                float a, bb;
                upk2(acc[j][0], a, bb);
                u64 pp0 = pk2(__expf(a + m0), __expf(bb + m0));
                upk2(acc[j][1], a, bb);
                u64 pp1 = pk2(__expf(a + m1), __expf(bb + m1));
                *(u64*)(pT + lane * STRD + qw + 2 * j)        = pp0;
                *(u64*)(pT + (lane + 32) * STRD + qw + 2 * j) = pp1;
                psum[j] = add2(psum[j], pp0);
                psum[j] = add2(psum[j], pp1);
            }
        }
        __syncwarp();   // pT rows are warp-private: warp-level sync suffices

        // ---- PV: o[j][dd] += p_pair[j](k) * v_dup(k, d) ----
        #pragma unroll 8
        for (int k = 0; k < 64; k++) {
            const float* prow = pT + k * STRD + qw;
            ulonglong2 pA = *(const ulonglong2*)(prow);       // (p_q0,p_q1),(p_q2,p_q3)
            ulonglong2 pB = *(const ulonglong2*)(prow + 4);
            float v0 = s_v[k * STRD + lane];
            float v1 = s_v[k * STRD + lane + 32];
            u64 v0d = pk2(v0, v0);
            u64 v1d = pk2(v1, v1);
            o[0][0] = fma2(pA.x, v0d, o[0][0]);
            o[0][1] = fma2(pA.x, v1d, o[0][1]);
            o[1][0] = fma2(pA.y, v0d, o[1][0]);
            o[1][1] = fma2(pA.y, v1d, o[1][1]);
            o[2][0] = fma2(pB.x, v0d, o[2][0]);
            o[2][1] = fma2(pB.x, v1d, o[2][1]);
            o[3][0] = fma2(pB.y, v0d, o[3][0]);
            o[3][1] = fma2(pB.y, v1d, o[3][1]);
        }
    }

    // ---- reduce row sums across lanes, normalize, store ----
    float sums[8];
    #pragma unroll
    for (int j = 0; j < 4; j++) upk2(psum[j], sums[2 * j], sums[2 * j + 1]);
    #pragma unroll
    for (int i = 0; i < 8; i++) {
        float s = sums[i];
        #pragma unroll
        for (int off = 16; off > 0; off >>= 1)
            s += __shfl_xor_sync(0xffffffffu, s, off);
        sums[i] = s;
    }

    float* outp = Out + base + (size_t)(qbase + qw) * DIM;
    #pragma unroll
    for (int j = 0; j < 4; j++) {
        float inv0 = 1.0f / sums[2 * j];
        float inv1 = 1.0f / sums[2 * j + 1];
        float a, bb;
        upk2(o[j][0], a, bb);
        outp[(2 * j + 0) * DIM + lane]      = a  * inv0;
        outp[(2 * j + 1) * DIM + lane]      = bb * inv1;
        upk2(o[j][1], a, bb);
        outp[(2 * j + 0) * DIM + lane + 32] = a  * inv0;
        outp[(2 * j + 1) * DIM + lane + 32] = bb * inv1;
    }
}

extern "C" void kernel_launch(void* const* d_in, const int* in_sizes, int n_in,
                              void* d_out, int out_size)
{
    const float* Q = (const float*)d_in[0];
    const float* K = (const float*)d_in[1];
    const float* V = (const float*)d_in[2];
    const float* M = (const float*)d_in[3];
    float* O = (float*)d_out;

    int smem_bytes = (4 * 64 * STRD + 64) * (int)sizeof(float);
    cudaFuncSetAttribute(sparse_attn_kernel,
                         cudaFuncAttributeMaxDynamicSharedMemorySize, smem_bytes);

    dim3 grid(NB, HEADS, BSZ);
    sparse_attn_kernel<<<grid, NTHREADS, smem_bytes>>>(Q, K, V, M, O);
}

// round 8
// speedup vs baseline: 8.1439x; 2.5968x over previous
#include <cuda_runtime.h>
#include <cuda_bf16.h>

// SparseSelfAttention via portable mma.sync bf16 (3-GEMM emulated fp32), FA2-style.
// BS=2,H=16,S=4096,D=64. CTA = 64 queries, 4 warps x 16 rows, 5 key chunks of 64.
// No tcgen05 (harness compiles family-portable sm_103: 'a'-features unavailable).

#define BSZ    2
#define HEADS  16
#define SEQ    4096
#define DIM    64
#define NCHUNK 5
#define CSHIFT 20.0f
#define NTHREADS 128

#define RS 144                 // smem row stride in BYTES (64 bf16 = 128B + 16B pad)

// smem byte offsets
#define SM_QH  0
#define SM_QL  (SM_QH + 64 * RS)
#define SM_KH  (SM_QL + 64 * RS)
#define SM_KL  (SM_KH + 64 * RS)
#define SM_VH  (SM_KL + 64 * RS)
#define SM_VL  (SM_VH + 64 * RS)
#define SM_M01 (SM_VL + 64 * RS)           // 64 floats
#define SM_TOTAL (SM_M01 + 64 * 4)

typedef unsigned int u32;

static __device__ __forceinline__ u32 smem_u32(const void* p) {
    u32 a;
    asm("{ .reg .u64 t; cvta.to.shared.u64 t, %1; cvt.u32.u64 %0, t; }" : "=r"(a) : "l"(p));
    return a;
}
// pack two floats -> bf16x2 {lo=a, hi=b}
static __device__ __forceinline__ u32 pkbf(float a, float b) {
    u32 r;
    asm("cvt.rn.bf16x2.f32 %0, %1, %2;" : "=r"(r) : "f"(b), "f"(a));
    return r;
}
static __device__ __forceinline__ float lo_f(u32 h) { return __uint_as_float(h << 16); }
static __device__ __forceinline__ float hi_f(u32 h) { return __uint_as_float(h & 0xFFFF0000u); }

static __device__ __forceinline__ void ldsm4(u32& r0, u32& r1, u32& r2, u32& r3, u32 a) {
    asm volatile("ldmatrix.sync.aligned.m8n8.x4.shared.b16 {%0,%1,%2,%3}, [%4];"
                 : "=r"(r0), "=r"(r1), "=r"(r2), "=r"(r3) : "r"(a));
}
static __device__ __forceinline__ void ldsm4t(u32& r0, u32& r1, u32& r2, u32& r3, u32 a) {
    asm volatile("ldmatrix.sync.aligned.m8n8.x4.trans.shared.b16 {%0,%1,%2,%3}, [%4];"
                 : "=r"(r0), "=r"(r1), "=r"(r2), "=r"(r3) : "r"(a));
}
static __device__ __forceinline__ void mma16816(float* c, u32 a0, u32 a1, u32 a2, u32 a3,
                                                u32 b0, u32 b1) {
    asm volatile(
        "mma.sync.aligned.m16n8k16.row.col.f32.bf16.bf16.f32 "
        "{%0,%1,%2,%3}, {%4,%5,%6,%7}, {%8,%9}, {%0,%1,%2,%3};"
        : "+f"(c[0]), "+f"(c[1]), "+f"(c[2]), "+f"(c[3])
        : "r"(a0), "r"(a1), "r"(a2), "r"(a3), "r"(b0), "r"(b1));
}

// key position for chunk c, slot k, query-block qb
static __device__ __forceinline__ int key_pos(int c, int k, int qb) {
    if (c == 0) return qb * 64 + k;
    int g = (c - 1) * 64 + k;
    int blk = g >> 2, off = g & 3;
    return blk * 64 + (off == 0 ? 0 : 60 + off);
}

extern __shared__ char smc[];

__global__ __launch_bounds__(NTHREADS)
void sparse_attn_mma(const float* __restrict__ Q,
                     const float* __restrict__ K,
                     const float* __restrict__ V,
                     const float* __restrict__ Mask,
                     float* __restrict__ Out)
{
    const int qb = blockIdx.x;
    const int h  = blockIdx.y;
    const int b  = blockIdx.z;
    const size_t bh_off = ((size_t)(b * HEADS + h)) * SEQ * DIM;
    const size_t q_off  = bh_off + (size_t)qb * 64 * DIM;

    const int tid  = threadIdx.x;
    const int L    = tid & 31;
    const int warp = tid >> 5;          // 0..3
    const int qw   = warp * 16;         // warp's first query row

    const u32 smb = smem_u32(smc);
    float* s_m01 = (float*)(smc + SM_M01);

    // ---- stage Q (64x64 fp32) -> bf16 hi/lo smem tiles ----
    #pragma unroll
    for (int i = 0; i < 8; i++) {
        int idx = tid + i * NTHREADS;           // 0..1023 float4s
        int row = idx >> 4, d4 = idx & 15;
        float4 f = *(const float4*)(Q + q_off + (size_t)row * DIM + d4 * 4);
        u32 h01 = pkbf(f.x, f.y), h23 = pkbf(f.z, f.w);
        u32 l01 = pkbf(f.x - lo_f(h01), f.y - hi_f(h01));
        u32 l23 = pkbf(f.z - lo_f(h23), f.w - hi_f(h23));
        *(uint2*)(smc + SM_QH + row * RS + d4 * 8) = make_uint2(h01, h23);
        *(uint2*)(smc + SM_QL + row * RS + d4 * 8) = make_uint2(l01, l23);
    }
    __syncthreads();

    // ---- load persistent Q A-fragments (4 k-tiles, hi+lo) ----
    u32 qh[4][4], ql[4][4];
    {
        int r    = L & 7;
        int rofs = ((L >> 3) & 1) * 8;          // m1,m3 -> rows+8
        int cofs = ((L >> 4) & 1) * 16;         // m2,m3 -> dims+8 (16B)
        #pragma unroll
        for (int kt = 0; kt < 4; kt++) {
            u32 a = smb + (qw + r + rofs) * RS + kt * 32 + cofs;
            ldsm4(qh[kt][0], qh[kt][1], qh[kt][2], qh[kt][3], a + SM_QH);
            ldsm4(ql[kt][0], ql[kt][1], ql[kt][2], ql[kt][3], a + SM_QL);
        }
    }

    float O[8][4];
    #pragma unroll
    for (int nt = 0; nt < 8; nt++)
        #pragma unroll
        for (int e = 0; e < 4; e++) O[nt][e] = 0.0f;
    float rs0 = 0.0f, rs1 = 0.0f;

    for (int c = 0; c < NCHUNK; c++) {
        __syncthreads();   // previous chunk's K/V readers done
        // ---- stage K,V chunk -> bf16 hi/lo (both natural [key][dim] layout) ----
        #pragma unroll
        for (int i = 0; i < 8; i++) {
            int idx = tid + i * NTHREADS;       // 0..1023 float4s
            int row = idx >> 4, d4 = idx & 15;
            int pos = key_pos(c, row, qb);
            float4 kf = *(const float4*)(K + bh_off + (size_t)pos * DIM + d4 * 4);
            u32 h01 = pkbf(kf.x, kf.y), h23 = pkbf(kf.z, kf.w);
            u32 l01 = pkbf(kf.x - lo_f(h01), kf.y - hi_f(h01));
            u32 l23 = pkbf(kf.z - lo_f(h23), kf.w - hi_f(h23));
            *(uint2*)(smc + SM_KH + row * RS + d4 * 8) = make_uint2(h01, h23);
            *(uint2*)(smc + SM_KL + row * RS + d4 * 8) = make_uint2(l01, l23);

            float4 vf = *(const float4*)(V + bh_off + (size_t)pos * DIM + d4 * 4);
            u32 vh01 = pkbf(vf.x, vf.y), vh23 = pkbf(vf.z, vf.w);
            u32 vl01 = pkbf(vf.x - lo_f(vh01), vf.y - hi_f(vh01));
            u32 vl23 = pkbf(vf.z - lo_f(vh23), vf.w - hi_f(vh23));
            *(uint2*)(smc + SM_VH + row * RS + d4 * 8) = make_uint2(vh01, vh23);
            *(uint2*)(smc + SM_VL + row * RS + d4 * 8) = make_uint2(vl01, vl23);
        }
        if (tid < 64) {
            int pos = key_pos(c, tid, qb);
            s_m01[tid] = (Mask[b * SEQ + pos] == 0.0f) ? 0.0f : 1.0f;
        }
        __syncthreads();

        // ---- QK: C = Qh*Kh + Qh*Kl + Ql*Kh ----
        float C[8][4];
        #pragma unroll
        for (int nt = 0; nt < 8; nt++)
            #pragma unroll
            for (int e = 0; e < 4; e++) C[nt][e] = 0.0f;

        {
            int r    = L & 7;
            int rofs = ((L >> 4) & 1) * 8;      // m2,m3 -> keys+8
            int cofs = ((L >> 3) & 1) * 16;     // m1,m3 -> dims+8
            #pragma unroll
            for (int kt = 0; kt < 4; kt++) {
                #pragma unroll
                for (int np = 0; np < 4; np++) {
                    u32 a = smb + (np * 16 + r + rofs) * RS + kt * 32 + cofs;
                    u32 b0, b1, b2, b3;
                    ldsm4(b0, b1, b2, b3, a + SM_KH);
                    mma16816(C[2 * np],     qh[kt][0], qh[kt][1], qh[kt][2], qh[kt][3], b0, b1);
                    mma16816(C[2 * np + 1], qh[kt][0], qh[kt][1], qh[kt][2], qh[kt][3], b2, b3);
                    mma16816(C[2 * np],     ql[kt][0], ql[kt][1], ql[kt][2], ql[kt][3], b0, b1);
                    mma16816(C[2 * np + 1], ql[kt][0], ql[kt][1], ql[kt][2], ql[kt][3], b2, b3);
                    ldsm4(b0, b1, b2, b3, a + SM_KL);
                    mma16816(C[2 * np],     qh[kt][0], qh[kt][1], qh[kt][2], qh[kt][3], b0, b1);
                    mma16816(C[2 * np + 1], qh[kt][0], qh[kt][1], qh[kt][2], qh[kt][3], b2, b3);
                }
            }
        }

        // ---- exp + mask + row-sum + split into P hi/lo A-fragments ----
        u32 ph[4][4], pl[4][4];
        #pragma unroll
        for (int nt = 0; nt < 8; nt++) {
            float2 mm = *(const float2*)(s_m01 + nt * 8 + 2 * (L & 3));
            float p0 = __expf(C[nt][0] - CSHIFT) * mm.x;
            float p1 = __expf(C[nt][1] - CSHIFT) * mm.y;
            float p2 = __expf(C[nt][2] - CSHIFT) * mm.x;
            float p3 = __expf(C[nt][3] - CSHIFT) * mm.y;
            rs0 += p0 + p1;
            rs1 += p2 + p3;
            u32 hA = pkbf(p0, p1), hB = pkbf(p2, p3);
            u32 lA = pkbf(p0 - lo_f(hA), p1 - hi_f(hA));
            u32 lB = pkbf(p2 - lo_f(hB), p3 - hi_f(hB));
            int kt = nt >> 1, e = (nt & 1) * 2;   // even nt -> a0,a1; odd -> a2,a3
            ph[kt][e] = hA; ph[kt][e + 1] = hB;
            pl[kt][e] = lA; pl[kt][e + 1] = lB;
        }

        // ---- PV: O += Ph*Vh + Ph*Vl + Pl*Vh ----
        {
            int r    = L & 7;
            int rofs = ((L >> 3) & 1) * 8;      // m1,m3 -> keys+8
            int cofs = ((L >> 4) & 1) * 16;     // m2,m3 -> dims+8
            #pragma unroll
            for (int kt = 0; kt < 4; kt++) {
                #pragma unroll
                for (int np = 0; np < 4; np++) {
                    u32 a = smb + (kt * 16 + r + rofs) * RS + np * 32 + cofs;
                    u32 b0, b1, b2, b3;
                    ldsm4t(b0, b1, b2, b3, a + SM_VH);
                    mma16816(O[2 * np],     ph[kt][0], ph[kt][1], ph[kt][2], ph[kt][3], b0, b1);
                    mma16816(O[2 * np + 1], ph[kt][0], ph[kt][1], ph[kt][2], ph[kt][3], b2, b3);
                    mma16816(O[2 * np],     pl[kt][0], pl[kt][1], pl[kt][2], pl[kt][3], b0, b1);
                    mma16816(O[2 * np + 1], pl[kt][0], pl[kt][1], pl[kt][2], pl[kt][3], b2, b3);
                    ldsm4t(b0, b1, b2, b3, a + SM_VL);
                    mma16816(O[2 * np],     ph[kt][0], ph[kt][1], ph[kt][2], ph[kt][3], b0, b1);
                    mma16816(O[2 * np + 1], ph[kt][0], ph[kt][1], ph[kt][2], ph[kt][3], b2, b3);
                }
            }
        }
    }

    // ---- reduce row sums over the 4 lanes sharing each row, normalize, store ----
    rs0 += __shfl_xor_sync(0xffffffffu, rs0, 1);
    rs0 += __shfl_xor_sync(0xffffffffu, rs0, 2);
    rs1 += __shfl_xor_sync(0xffffffffu, rs1, 1);
    rs1 += __shfl_xor_sync(0xffffffffu, rs1, 2);
    float inv0 = 1.0f / rs0;
    float inv1 = 1.0f / rs1;

    {
        int row0 = qw + (L >> 2);
        int col  = 2 * (L & 3);
        float* o0 = Out + q_off + (size_t)row0 * DIM + col;
        float* o1 = o0 + 8 * DIM;
        #pragma unroll
        for (int nt = 0; nt < 8; nt++) {
            *(float2*)(o0 + nt * 8) = make_float2(O[nt][0] * inv0, O[nt][1] * inv0);
            *(float2*)(o1 + nt * 8) = make_float2(O[nt][2] * inv1, O[nt][3] * inv1);
        }
    }
}

extern "C" void kernel_launch(void* const* d_in, const int* in_sizes, int n_in,
                              void* d_out, int out_size)
{
    const float* Q = (const float*)d_in[0];
    const float* K = (const float*)d_in[1];
    const float* V = (const float*)d_in[2];
    const float* M = (const float*)d_in[3];
    float* O = (float*)d_out;

    cudaFuncSetAttribute(sparse_attn_mma,
                         cudaFuncAttributeMaxDynamicSharedMemorySize, SM_TOTAL);

    dim3 grid(SEQ / 64, HEADS, BSZ);    // (64, 16, 2)
    sparse_attn_mma<<<grid, NTHREADS, SM_TOTAL>>>(Q, K, V, M, O);
}